// round 15
// baseline (speedup 1.0000x reference)
#include <cuda_runtime.h>
#include <cuda_fp16.h>
#include <cstdint>

// ---------------- problem constants ----------------
constexpr int B   = 128;
constexpr int N   = 4096;
constexpr int OUT = 64;
constexpr int F1 = 64, F2 = 128, F3 = 256;

constexpr int TILE  = 256;          // points per work item
constexpr int MAXT  = N / TILE;     // 16
constexpr int MAXW  = B * MAXT;     // 2048 work items (per half)
constexpr int GRID  = 304;          // 2 CTAs per SM (even=lo half, odd=hi half)
constexpr int NT    = 256;          // 8 warps per CTA

// half strides with +8 pad -> conflict-free fragment access
constexpr int S1H = 72;             // h1 / wt2 rows (k-dim 64)
constexpr int S3H = 136;            // h2 / wt3 rows (k-dim 128)
constexpr int S1W = S1H / 2;        // 36 words
constexpr int S3W = S3H / 2;        // 68 words

__device__ float g_agg[B * F3];
__device__ int   g_work2[2];        // one counter per feature-half
__device__ __align__(16) __half wt2g[F2 * S1H];   // [128 n][72 k] fp16
__device__ __align__(16) __half wt3g[F3 * S3H];   // [256 n][136 k] fp16

// ---------------- smem layout (bytes) ----------------
constexpr int OFF_W1  = 0;                          // 128 floats
constexpr int OFF_B1  = 512;                        // 64 floats
constexpr int OFF_POP = 768;                        // 2 ints (w, len)
constexpr int OFF_H1  = 1024;                       // 256*72 halves = 36864 B
constexpr int OFF_H2  = OFF_H1 + TILE * S1H * 2;    // 37888
constexpr int SMEM_TOTAL = OFF_H2 + TILE * S3H * 2; // 107520 B (x2 CTAs = 210 KB/SM)

__device__ __forceinline__ void mma_f16(float* d,
                                        uint32_t a0, uint32_t a1, uint32_t a2, uint32_t a3,
                                        uint32_t b0, uint32_t b1) {
    asm volatile(
        "mma.sync.aligned.m16n8k16.row.col.f32.f16.f16.f32 "
        "{%0,%1,%2,%3}, {%4,%5,%6,%7}, {%8,%9}, {%0,%1,%2,%3};"
        : "+f"(d[0]), "+f"(d[1]), "+f"(d[2]), "+f"(d[3])
        : "r"(a0), "r"(a1), "r"(a2), "r"(a3), "r"(b0), "r"(b1));
}

__device__ __forceinline__ void ldsm4(uint32_t& r0, uint32_t& r1, uint32_t& r2, uint32_t& r3,
                                      uint32_t saddr) {
    asm volatile("ldmatrix.sync.aligned.m8n8.x4.shared.b16 {%0,%1,%2,%3}, [%4];"
                 : "=r"(r0), "=r"(r1), "=r"(r2), "=r"(r3) : "r"(saddr));
}

__device__ __forceinline__ uint32_t packh2(float lo, float hi) {
    __half2 h = __floats2half2_rn(lo, hi);
    return *reinterpret_cast<uint32_t*>(&h);
}

__device__ __forceinline__ uint32_t smem_u32(const void* p) {
    uint32_t a;
    asm("{ .reg .u64 t; cvta.to.shared.u64 t, %1; cvt.u32.u64 %0, t; }" : "=r"(a) : "l"(p));
    return a;
}

// ---------------- prep: reset counters/agg + convert weights ----------------
__global__ void prep_kernel(const float* __restrict__ w2, const float* __restrict__ w3) {
    int i = blockIdx.x * 256 + threadIdx.x;
    if (i < 2) g_work2[i] = 0;
    if (i < B * F3) g_agg[i] = 0.0f;
    if (i < F1 * F2) {           // w2: [64 k][128 n] -> wt2g[n][k]
        int k = i >> 7, n = i & 127;
        wt2g[n * S1H + k] = __float2half_rn(w2[i]);
    }
    if (i < F2 * F3) {           // w3: [128 k][256 n] -> wt3g[n][k]
        int k = i >> 8, n = i & 255;
        wt3g[n * S3H + k] = __float2half_rn(w3[i]);
    }
}

// ---------------- phi: split-N dual-CTA persistent work-stealing ----------------
__global__ void __launch_bounds__(NT, 2)
phi_mma_kernel(const float* __restrict__ points, const int* __restrict__ lengths,
               const float* __restrict__ w1, const float* __restrict__ b1,
               const float* __restrict__ b2, const float* __restrict__ b3)
{
    extern __shared__ char smem[];
    float* w1s  = reinterpret_cast<float*>(smem + OFF_W1);
    float* b1s  = reinterpret_cast<float*>(smem + OFF_B1);
    int*   spop = reinterpret_cast<int*>(smem + OFF_POP);
    uint32_t* h1w = reinterpret_cast<uint32_t*>(smem + OFF_H1);
    uint32_t* h2w = reinterpret_cast<uint32_t*>(smem + OFF_H2);
    const uint32_t sb = smem_u32(smem);

    const int half = blockIdx.x & 1;    // feature half: 0 -> cols 0-127, 1 -> 128-255
    const int tid  = threadIdx.x;
    const int lane = tid & 31;
    const int wid  = tid >> 5;          // 0..7
    const int g    = lane >> 2;         // row group 0..7
    const int c    = lane & 3;          // col-in-group 0..3
    const int nb2  = wid * 16;          // L2 n-slice (16 cols, 8 warps cover 128)
    const int gb3  = half * 128 + wid * 16;   // L3 global col base

    if (tid < 128) w1s[tid] = w1[tid];
    else if (tid < 192) b1s[tid - 128] = b1[tid - 128];

    // ---- persistent B fragments + biases (registers) ----
    const uint32_t* w2w = reinterpret_cast<const uint32_t*>(wt2g);
    const uint32_t* w3w = reinterpret_cast<const uint32_t*>(wt3g);
    uint32_t b2r[2][4][2];
#pragma unroll
    for (int nt = 0; nt < 2; nt++)
#pragma unroll
        for (int ks = 0; ks < 4; ks++) {
            const int base = (nb2 + nt * 8 + g) * S1W + ks * 8 + c;
            b2r[nt][ks][0] = w2w[base];
            b2r[nt][ks][1] = w2w[base + 4];
        }
    uint32_t b3r[2][8][2];
#pragma unroll
    for (int nt = 0; nt < 2; nt++)
#pragma unroll
        for (int ks = 0; ks < 8; ks++) {
            const int base = (gb3 + nt * 8 + g) * S3W + ks * 8 + c;
            b3r[nt][ks][0] = w3w[base];
            b3r[nt][ks][1] = w3w[base + 4];
        }
    float bb2[2][2], bb3[2][2];
#pragma unroll
    for (int nt = 0; nt < 2; nt++) {
        bb2[nt][0] = b2[nb2 + nt * 8 + 2 * c];
        bb2[nt][1] = b2[nb2 + nt * 8 + 2 * c + 1];
        bb3[nt][0] = b3[gb3 + nt * 8 + 2 * c];
        bb3[nt][1] = b3[gb3 + nt * 8 + 2 * c + 1];
    }

    // ---- ldmatrix per-lane base addresses ----
    const int tsel = lane >> 3, rr = lane & 7;
    const int lrow = (tsel & 1) * 8 + rr;
    const int lcol = (tsel >> 1) * 4;
    const uint32_t a1base = sb + OFF_H1 + (lrow * S1W + lcol) * 4;
    const uint32_t a2base = sb + OFF_H2 + (lrow * S3W + lcol) * 4;

    // ---- tid0 pop from this half's counter, skipping invalid items ----
    auto pop = [&]() {
        int ww = atomicAdd(&g_work2[half], 1);
        int ll = 0;
        while (ww < MAXW) {
            ll = lengths[ww & (B - 1)];
            if ((ww >> 7) * TILE < ll) break;
            ww = atomicAdd(&g_work2[half], 1);
        }
        spop[0] = ww; spop[1] = ll;
    };

    // ---- L1 split: load points (MLP=4) / compute+store (conflict-free quad map) ----
    const int p0_ = tid >> 2, cl_ = tid & 3;   // quad: 4 threads share a point
    auto l1_load = [&](int ww, int ll, float2* preg) {
        const int bm = (ww >> 7) * TILE;
        const int rw = min(TILE, ll - bm);
        const int bx = ww & (B - 1);
#pragma unroll
        for (int pass = 0; pass < 4; pass++) {
            const int p = p0_ + pass * 64;
            preg[pass] = (p < rw)
                ? reinterpret_cast<const float2*>(points)[(long long)bx * N + bm + p]
                : make_float2(0.0f, 0.0f);
        }
        return rw;
    };
    auto l1_store = [&](const float2* preg, int rw) {
#pragma unroll
        for (int pass = 0; pass < 4; pass++) {
            const int p = p0_ + pass * 64;
            if (p < rw) {
                const float x = preg[pass].x, y = preg[pass].y;
#pragma unroll
                for (int i = 0; i < 8; i++) {
                    const int f = 8 * i + 2 * cl_;
                    float v0 = fmaxf(fmaf(x, w1s[f],     fmaf(y, w1s[64 + f],     b1s[f])),     0.0f);
                    float v1 = fmaxf(fmaf(x, w1s[f + 1], fmaf(y, w1s[64 + f + 1], b1s[f + 1])), 0.0f);
                    h1w[p * S1W + 4 * i + cl_] = packh2(v0, v1);   // bank 4p+cl: conflict-free
                }
            }
        }
    };

    if (tid == 0) pop();
    __syncthreads();
    int w = spop[0], len = spop[1];
    if (w < MAXW) {
        float2 preg[4];
        int rw = l1_load(w, len, preg);
        l1_store(preg, rw);
    }
    __syncthreads();    // h1 ready

    while (w < MAXW) {
        const int bidx   = w & (B - 1);
        const int base_m = (w >> 7) * TILE;
        const int rows   = min(TILE, len - base_m);
        const int mfmax  = (rows + 15) >> 4;

        // ---- phase B: layer 2 (all 128 cols, duplicated across halves) ----
        for (int mf = 0; mf < mfmax; mf++) {
            float acc[2][4];
#pragma unroll
            for (int nt = 0; nt < 2; nt++)
#pragma unroll
                for (int j = 0; j < 4; j++) acc[nt][j] = 0.0f;
#pragma unroll
            for (int ks = 0; ks < 4; ks++) {
                uint32_t a0, a1, a2, a3;
                ldsm4(a0, a1, a2, a3, a1base + (mf * 16 * S1W + ks * 8) * 4);
#pragma unroll
                for (int nt = 0; nt < 2; nt++)
                    mma_f16(acc[nt], a0, a1, a2, a3, b2r[nt][ks][0], b2r[nt][ks][1]);
            }
            const int r0 = mf * 16 + g, r1 = r0 + 8;
#pragma unroll
            for (int nt = 0; nt < 2; nt++) {
                const int cw = wid * 8 + nt * 4 + c;
                h2w[r0 * S3W + cw] = packh2(fmaxf(acc[nt][0] + bb2[nt][0], 0.0f),
                                            fmaxf(acc[nt][1] + bb2[nt][1], 0.0f));
                h2w[r1 * S3W + cw] = packh2(fmaxf(acc[nt][2] + bb2[nt][0], 0.0f),
                                            fmaxf(acc[nt][3] + bb2[nt][1], 0.0f));
            }
        }
        if (tid == 0) pop();
        __syncthreads();    // h2 ready + next item known; L2 done reading h1
        const int wn = spop[0], lenn = spop[1];

        // ---- phase C: next-tile LDGs first (hide under L3), L3, flush, L1 stores ----
        float2 preg[4];
        int rwn = 0;
        if (wn < MAXW) rwn = l1_load(wn, lenn, preg);

        float rm[2][2] = {{0.0f, 0.0f}, {0.0f, 0.0f}};
        for (int mf = 0; mf < mfmax; mf++) {
            float acc[2][4];
#pragma unroll
            for (int nt = 0; nt < 2; nt++)
#pragma unroll
                for (int j = 0; j < 4; j++) acc[nt][j] = 0.0f;
#pragma unroll
            for (int ks = 0; ks < 8; ks++) {
                uint32_t a0, a1, a2, a3;
                ldsm4(a0, a1, a2, a3, a2base + (mf * 16 * S3W + ks * 8) * 4);
#pragma unroll
                for (int nt = 0; nt < 2; nt++)
                    mma_f16(acc[nt], a0, a1, a2, a3, b3r[nt][ks][0], b3r[nt][ks][1]);
            }
            const int r0 = base_m + mf * 16 + g;
            const int r1 = r0 + 8;
            const bool v0 = r0 < len, v1 = r1 < len;
#pragma unroll
            for (int nt = 0; nt < 2; nt++) {
                float x0 = v0 ? fmaxf(acc[nt][0] + bb3[nt][0], 0.0f) : 0.0f;
                float x1 = v0 ? fmaxf(acc[nt][1] + bb3[nt][1], 0.0f) : 0.0f;
                float y0 = v1 ? fmaxf(acc[nt][2] + bb3[nt][0], 0.0f) : 0.0f;
                float y1 = v1 ? fmaxf(acc[nt][3] + bb3[nt][1], 0.0f) : 0.0f;
                rm[nt][0] = fmaxf(rm[nt][0], fmaxf(x0, y0));
                rm[nt][1] = fmaxf(rm[nt][1], fmaxf(x1, y1));
            }
        }
#pragma unroll
        for (int nt = 0; nt < 2; nt++) {
#pragma unroll
            for (int j = 0; j < 2; j++) {
                float v = rm[nt][j];
                v = fmaxf(v, __shfl_xor_sync(0xFFFFFFFFu, v, 4));
                v = fmaxf(v, __shfl_xor_sync(0xFFFFFFFFu, v, 8));
                v = fmaxf(v, __shfl_xor_sync(0xFFFFFFFFu, v, 16));
                if (g == 0)
                    atomicMax(reinterpret_cast<int*>(&g_agg[bidx * F3 + gb3 + nt * 8 + 2 * c + j]),
                              __float_as_int(v));
            }
        }

        // next tile's L1 stores (h1 free since sync2; C read only h2)
        if (wn < MAXW) l1_store(preg, rwn);
        w = wn; len = lenn;
        __syncthreads();    // h1(next) ready; all h2 reads done before next B writes
    }
}

__global__ void __launch_bounds__(256)
rho_kernel(const float* __restrict__ r1w, const float* __restrict__ r1b,
           const float* __restrict__ r2w, const float* __restrict__ r2b,
           const float* __restrict__ r3w, const float* __restrict__ r3b,
           float* __restrict__ out)
{
    __shared__ float a[256], z1[256], z2[128];
    const int b   = blockIdx.x;
    const int tid = threadIdx.x;

    a[tid] = g_agg[b * F3 + tid];
    __syncthreads();

    float acc = r1b[tid];
#pragma unroll 4
    for (int k = 0; k < 256; k++) acc = fmaf(a[k], r1w[k * 256 + tid], acc);
    z1[tid] = fmaxf(acc, 0.0f);
    __syncthreads();

    if (tid < 128) {
        float acc2 = r2b[tid];
#pragma unroll 4
        for (int k = 0; k < 256; k++) acc2 = fmaf(z1[k], r2w[k * 128 + tid], acc2);
        z2[tid] = fmaxf(acc2, 0.0f);
    }
    __syncthreads();

    if (tid < 64) {
        float acc3 = r3b[tid];
#pragma unroll 4
        for (int k = 0; k < 128; k++) acc3 = fmaf(z2[k], r3w[k * 64 + tid], acc3);
        out[b * OUT + tid] = acc3;
    }
}

// ---------------- launch ----------------
extern "C" void kernel_launch(void* const* d_in, const int* in_sizes, int n_in,
                              void* d_out, int out_size)
{
    (void)in_sizes; (void)n_in; (void)out_size;
    const float* points = (const float*)d_in[0];
    const int*   lengths= (const int*)  d_in[1];
    const float* w1  = (const float*)d_in[2];
    const float* b1  = (const float*)d_in[3];
    const float* w2  = (const float*)d_in[4];
    const float* b2  = (const float*)d_in[5];
    const float* w3  = (const float*)d_in[6];
    const float* b3  = (const float*)d_in[7];
    const float* r1w = (const float*)d_in[8];
    const float* r1b = (const float*)d_in[9];
    const float* r2w = (const float*)d_in[10];
    const float* r2b = (const float*)d_in[11];
    const float* r3w = (const float*)d_in[12];
    const float* r3b = (const float*)d_in[13];

    cudaFuncSetAttribute(phi_mma_kernel,
                         cudaFuncAttributeMaxDynamicSharedMemorySize, SMEM_TOTAL);

    prep_kernel<<<128, 256>>>(w2, w3);
    phi_mma_kernel<<<GRID, NT, SMEM_TOTAL>>>(points, lengths, w1, b1, b2, b3);
    rho_kernel<<<B, 256>>>(r1w, r1b, r2w, r2b, r3w, r3b, (float*)d_out);
}